// round 16
// baseline (speedup 1.0000x reference)
#include <cuda_runtime.h>
#include <cstdint>

#define NB 32
#define NT 1024
#define ND 512
#define NU 64

// -------- scratch (device globals) --------
__device__ float g_C[2ull * NB * ND * 128];   // X^T@[w2|w3] fp32  (16.8MB)
__device__ uint32_t g_WH[512 * 128];          // [t-pair][u] packed f16x2 hi of [w2|w3]
__device__ uint32_t g_WL[512 * 128];          //                  residual lo
__device__ uint32_t g_MH[64ull * 256 * 64];   // [sb][d-pair][u] packed f16x2 hi of M
__device__ uint32_t g_ML[64ull * 256 * 64];
__device__ float g_E[2 * NB * NT];
__device__ float g_W[2 * NB * NT];

// -------- helpers --------
__device__ __forceinline__ uint32_t smem_u32(const void* p) {
    uint32_t a;
    asm("{ .reg .u64 t; cvta.to.shared.u64 t, %1; cvt.u32.u64 %0, t; }" : "=r"(a) : "l"(p));
    return a;
}
// split (x0,x1) -> packed f16x2 hi (lo half = x0) + packed residual lo
__device__ __forceinline__ void split_pair(float x0, float x1, uint32_t& hi, uint32_t& lo) {
    asm("cvt.rn.f16x2.f32 %0, %1, %2;" : "=r"(hi) : "f"(x1), "f"(x0));
    float h0, h1;
    asm("{ .reg .b16 a, b; mov.b32 {a, b}, %2; cvt.f32.f16 %0, a; cvt.f32.f16 %1, b; }"
        : "=f"(h0), "=f"(h1) : "r"(hi));
    float l0 = x0 - h0, l1 = x1 - h1;
    asm("cvt.rn.f16x2.f32 %0, %1, %2;" : "=r"(lo) : "f"(l1), "f"(l0));
}
__device__ __forceinline__ void mma_f16(float* c, const uint32_t* a, const uint32_t* b) {
    asm volatile(
        "mma.sync.aligned.m16n8k16.row.col.f32.f16.f16.f32 "
        "{%0,%1,%2,%3}, {%4,%5,%6,%7}, {%8,%9}, {%0,%1,%2,%3};"
        : "+f"(c[0]), "+f"(c[1]), "+f"(c[2]), "+f"(c[3])
        : "r"(a[0]), "r"(a[1]), "r"(a[2]), "r"(a[3]), "r"(b[0]), "r"(b[1]));
}
__device__ __forceinline__ void cp16(uint32_t dst, const void* src) {
    asm volatile("cp.async.cg.shared.global [%0], [%1], 16;" :: "r"(dst), "l"(src));
}
#define CP_COMMIT() asm volatile("cp.async.commit_group;" ::: "memory")
#define CP_WAIT0() asm volatile("cp.async.wait_group 0;" ::: "memory")

// ============================================================================
// K0: pre-split [w2|w3] into packed f16x2 t-pair words.
// ============================================================================
__global__ void __launch_bounds__(256) k0_wsplit(const float* __restrict__ w2,
                                                 const float* __restrict__ w3) {
    int i = blockIdx.x * 256 + threadIdx.x;  // 512*128
    int u = i & 127, tp = i >> 7;
    const float* W = (u < 64) ? (w2 + u) : (w3 + (u - 64));
    float v0 = W[(size_t)(2 * tp) * NU];
    float v1 = W[(size_t)(2 * tp + 1) * NU];
    uint32_t hi, lo;
    split_pair(v0, v1, hi, lo);
    g_WH[i] = hi;
    g_WL[i] = lo;
}

// ============================================================================
// K1: C[s][b] = X_s[b]^T @ [w2|w3]   M=128(d) N=128(u) K=1024(t)
// 8 warps (2M x 4N), warp tile 64x32, Kc=16 double-buffered cp.async.
// Chunk phases: [wait; bar; SPLIT A fp32->f16 tiles (1x per element);
//                issue next cp; bar; pure LDS+HMMA mainloop].
// ============================================================================
#define K1S 132
#define K1BS 136
__global__ void __launch_bounds__(256, 2) k1_xtw(const float* __restrict__ x1,
                                                 const float* __restrict__ x2) {
    __shared__ __align__(16) float sA32[2][16][K1S];      // [t][d] fp32
    __shared__ __align__(16) uint32_t sAH[8][K1BS];       // [t-pair][d] f16x2 hi
    __shared__ __align__(16) uint32_t sAL[8][K1BS];       //            residual lo
    __shared__ __align__(16) uint32_t sB[2][2][8][K1BS];  // [buf][hi/lo][t-pair][u]
    const int tid = threadIdx.x, wid = tid >> 5, lane = tid & 31;
    const int gid = lane >> 2, tig = lane & 3;
    const int dt = blockIdx.x, b = blockIdx.y, s = blockIdx.z;
    const float* __restrict__ X = s ? x2 : x1;
    const int d0 = dt * 128;
    const int wm = (wid >> 2) * 64, wn = (wid & 3) * 32;

    float acc[4][4][4];
#pragma unroll
    for (int i = 0; i < 4; i++)
#pragma unroll
        for (int j = 0; j < 4; j++)
#pragma unroll
            for (int q = 0; q < 4; q++) acc[i][j][q] = 0.f;

    const uint32_t aB = smem_u32(&sA32[0][0][0]);
    const uint32_t bB = smem_u32(&sB[0][0][0][0]);
    const uint32_t aBuf = 16 * K1S * 4;
    const uint32_t bBuf = 2 * 8 * K1BS * 4;

    auto issue = [&](int ch, int bi) {
        const int k0 = ch * 16;
#pragma unroll
        for (int it = 0; it < 2; it++) {
            int ff = tid + it * 256;
            int r = ff >> 5, c = (ff & 31) * 4;
            cp16(aB + bi * aBuf + (uint32_t)(r * K1S + c) * 4,
                 X + ((size_t)b * NT + k0 + r) * ND + d0 + c);
        }
#pragma unroll
        for (int it = 0; it < 2; it++) {
            int ff = tid + it * 256;
            int sp = ff >> 8, r = (ff >> 5) & 7, c = (ff & 31) * 4;
            const uint32_t* src = (sp ? g_WL : g_WH) + (size_t)(ch * 8 + r) * 128 + c;
            cp16(bB + bi * bBuf + (uint32_t)((sp * 8 + r) * K1BS + c) * 4, src);
        }
        CP_COMMIT();
    };

    issue(0, 0);
    for (int ch = 0; ch < 64; ch++) {
        const int bi = ch & 1;
        CP_WAIT0();
        __syncthreads();  // cp(ch) visible; prior mma done (frees sA16/sB[bi^1])
        // ---- split phase: warp w handles t-pair tp=w, lane l handles d = l*4..l*4+3
        {
            const float4 va = *(const float4*)&sA32[bi][2 * wid][lane * 4];
            const float4 vb = *(const float4*)&sA32[bi][2 * wid + 1][lane * 4];
            uint4 h, l;
            split_pair(va.x, vb.x, h.x, l.x);
            split_pair(va.y, vb.y, h.y, l.y);
            split_pair(va.z, vb.z, h.z, l.z);
            split_pair(va.w, vb.w, h.w, l.w);
            *(uint4*)&sAH[wid][lane * 4] = h;
            *(uint4*)&sAL[wid][lane * 4] = l;
        }
        if (ch + 1 < 64) issue(ch + 1, bi ^ 1);
        __syncthreads();  // sA16 ready
        // ---- pure mainloop
        uint32_t bh[4][2], bl[4][2];
#pragma unroll
        for (int ni = 0; ni < 4; ni++) {
            const int un = wn + ni * 8 + gid;
            bh[ni][0] = sB[bi][0][tig][un];
            bh[ni][1] = sB[bi][0][tig + 4][un];
            bl[ni][0] = sB[bi][1][tig][un];
            bl[ni][1] = sB[bi][1][tig + 4][un];
        }
#pragma unroll
        for (int mi = 0; mi < 4; mi++) {
            const int dm = wm + mi * 16 + gid;
            uint32_t ah[4], al[4];
            ah[0] = sAH[tig][dm];
            ah[1] = sAH[tig][dm + 8];
            ah[2] = sAH[tig + 4][dm];
            ah[3] = sAH[tig + 4][dm + 8];
            al[0] = sAL[tig][dm];
            al[1] = sAL[tig][dm + 8];
            al[2] = sAL[tig + 4][dm];
            al[3] = sAL[tig + 4][dm + 8];
#pragma unroll
            for (int ni = 0; ni < 4; ni++) mma_f16(acc[mi][ni], ah, bh[ni]);
#pragma unroll
            for (int ni = 0; ni < 4; ni++) mma_f16(acc[mi][ni], al, bh[ni]);
#pragma unroll
            for (int ni = 0; ni < 4; ni++) mma_f16(acc[mi][ni], ah, bl[ni]);
        }
    }
    float* dst = g_C + (size_t)(s * NB + b) * ND * 128 + (size_t)d0 * 128;
#pragma unroll
    for (int mi = 0; mi < 4; mi++) {
        int r0 = wm + mi * 16 + gid, r1 = r0 + 8;
#pragma unroll
        for (int ni = 0; ni < 4; ni++) {
            int col = wn + ni * 8 + 2 * tig;
            *(float2*)(dst + (size_t)r0 * 128 + col) =
                make_float2(acc[mi][ni][0], acc[mi][ni][1]);
            *(float2*)(dst + (size_t)r1 * 128 + col) =
                make_float2(acc[mi][ni][2], acc[mi][ni][3]);
        }
    }
}

// ============================================================================
// K_prep: M[sb][d][u] = C[1-s][b][d][u] + C[s][b][d][64+u] + w1[d][u]
// -> packed f16x2 d-pair words g_MH/g_ML [sb][dp][u]
// ============================================================================
__global__ void __launch_bounds__(256) k_prep(const float* __restrict__ w1) {
    int i = blockIdx.x * 256 + threadIdx.x;  // 64*256*64 = 1,048,576
    int u = i & 63;
    int dp = (i >> 6) & 255;
    int sb = i >> 14;
    int s = sb >> 5, b = sb & 31;
    const float* C0 = g_C + ((size_t)((1 - s) * NB + b) * ND << 7);
    const float* C1 = g_C + ((size_t)sb * ND << 7);
    int d0 = 2 * dp, d1 = 2 * dp + 1;
    float m0 = C0[((size_t)d0 << 7) + u] + C1[((size_t)d0 << 7) + 64 + u] + w1[d0 * NU + u];
    float m1 = C0[((size_t)d1 << 7) + u] + C1[((size_t)d1 << 7) + 64 + u] + w1[d1 * NU + u];
    uint32_t hi, lo;
    split_pair(m0, m1, hi, lo);
    g_MH[i] = hi;
    g_ML[i] = lo;
}

// ============================================================================
// K2: e = 10*sum_u tanh(X@M)*we    M=256(t) N=64(u) K=512(d)
// grid 256 (single wave). 8 warps (4M x 2N), warp tile 64t x 32u, Kc=16.
// Same staged-split structure as K1.
// ============================================================================
#define K2AS 16
#define K2TS 264
#define K2BS 72
__global__ void __launch_bounds__(256, 2) k2_he(const float* __restrict__ x1,
                                                const float* __restrict__ x2,
                                                const float* __restrict__ we) {
    __shared__ __align__(16) float sA32[2][256][K2AS];    // [t][d] fp32
    __shared__ __align__(16) uint32_t sAH[8][K2TS];       // [d-pair][t]
    __shared__ __align__(16) uint32_t sAL[8][K2TS];
    __shared__ __align__(16) uint32_t sB[2][2][8][K2BS];  // [buf][hi/lo][d-pair][u]
    __shared__ float wes[64];
    __shared__ float red[256][2];
    const int tid = threadIdx.x, wid = tid >> 5, lane = tid & 31;
    const int gid = lane >> 2, tig = lane & 3;
    const int tt = blockIdx.x, b = blockIdx.y, s = blockIdx.z;
    const float* __restrict__ X = s ? x2 : x1;
    const int t0 = tt * 256, sb = s * NB + b;
    const int wm = (wid >> 1) * 64, wn = (wid & 1) * 32;

    if (tid < 64) wes[tid] = we[tid];

    float acc[4][4][4];
#pragma unroll
    for (int i = 0; i < 4; i++)
#pragma unroll
        for (int j = 0; j < 4; j++)
#pragma unroll
            for (int q = 0; q < 4; q++) acc[i][j][q] = 0.f;

    const uint32_t aB = smem_u32(&sA32[0][0][0]);
    const uint32_t bB = smem_u32(&sB[0][0][0][0]);
    const uint32_t aBuf = 256 * K2AS * 4;
    const uint32_t bBuf = 2 * 8 * K2BS * 4;
    const size_t mBase = (size_t)sb * 256 * 64;

    auto issue = [&](int ch, int bi) {
        const int k0 = ch * 16;
#pragma unroll
        for (int it = 0; it < 4; it++) {
            int ff = tid + it * 256;
            int r = ff >> 2, c = (ff & 3) * 4;
            cp16(aB + bi * aBuf + (uint32_t)(r * K2AS + c) * 4,
                 X + ((size_t)b * NT + t0 + r) * ND + k0 + c);
        }
        {
            int sp = tid >> 7, r = (tid >> 4) & 7, c = (tid & 15) * 4;
            const uint32_t* src = (sp ? g_ML : g_MH) + mBase + (size_t)(ch * 8 + r) * 64 + c;
            cp16(bB + bi * bBuf + (uint32_t)((sp * 8 + r) * K2BS + c) * 4, src);
        }
        CP_COMMIT();
    };

    issue(0, 0);
    for (int ch = 0; ch < 32; ch++) {
        const int bi = ch & 1;
        CP_WAIT0();
        __syncthreads();
        // ---- split phase: thread t=tid handles its full row (8 d-pairs)
        {
            const float* Ar = &sA32[bi][tid][0];
            float4 q0 = *(const float4*)(Ar + 0);
            float4 q1 = *(const float4*)(Ar + 4);
            float4 q2 = *(const float4*)(Ar + 8);
            float4 q3 = *(const float4*)(Ar + 12);
            uint32_t h, l;
            split_pair(q0.x, q0.y, h, l); sAH[0][tid] = h; sAL[0][tid] = l;
            split_pair(q0.z, q0.w, h, l); sAH[1][tid] = h; sAL[1][tid] = l;
            split_pair(q1.x, q1.y, h, l); sAH[2][tid] = h; sAL[2][tid] = l;
            split_pair(q1.z, q1.w, h, l); sAH[3][tid] = h; sAL[3][tid] = l;
            split_pair(q2.x, q2.y, h, l); sAH[4][tid] = h; sAL[4][tid] = l;
            split_pair(q2.z, q2.w, h, l); sAH[5][tid] = h; sAL[5][tid] = l;
            split_pair(q3.x, q3.y, h, l); sAH[6][tid] = h; sAL[6][tid] = l;
            split_pair(q3.z, q3.w, h, l); sAH[7][tid] = h; sAL[7][tid] = l;
        }
        if (ch + 1 < 32) issue(ch + 1, bi ^ 1);
        __syncthreads();
        // ---- pure mainloop
        uint32_t bh[4][2], bl[4][2];
#pragma unroll
        for (int ni = 0; ni < 4; ni++) {
            const int un = wn + ni * 8 + gid;
            bh[ni][0] = sB[bi][0][tig][un];
            bh[ni][1] = sB[bi][0][tig + 4][un];
            bl[ni][0] = sB[bi][1][tig][un];
            bl[ni][1] = sB[bi][1][tig + 4][un];
        }
#pragma unroll
        for (int mi = 0; mi < 4; mi++) {
            const int tr = wm + mi * 16 + gid;
            uint32_t ah[4], al[4];
            ah[0] = sAH[tig][tr];
            ah[1] = sAH[tig][tr + 8];
            ah[2] = sAH[tig + 4][tr];
            ah[3] = sAH[tig + 4][tr + 8];
            al[0] = sAL[tig][tr];
            al[1] = sAL[tig][tr + 8];
            al[2] = sAL[tig + 4][tr];
            al[3] = sAL[tig + 4][tr + 8];
#pragma unroll
            for (int ni = 0; ni < 4; ni++) mma_f16(acc[mi][ni], ah, bh[ni]);
#pragma unroll
            for (int ni = 0; ni < 4; ni++) mma_f16(acc[mi][ni], al, bh[ni]);
#pragma unroll
            for (int ni = 0; ni < 4; ni++) mma_f16(acc[mi][ni], ah, bl[ni]);
        }
    }
    // epilogue: e(t) = 10 * sum_u tanh(h[t,u]) * we[u]
#pragma unroll
    for (int mi = 0; mi < 4; mi++) {
        int r0 = wm + mi * 16 + gid, r1 = r0 + 8;
        float p0 = 0.f, p1 = 0.f;
#pragma unroll
        for (int ni = 0; ni < 4; ni++) {
            int u = wn + ni * 8 + 2 * tig;
            p0 += tanhf(acc[mi][ni][0]) * wes[u] + tanhf(acc[mi][ni][1]) * wes[u + 1];
            p1 += tanhf(acc[mi][ni][2]) * wes[u] + tanhf(acc[mi][ni][3]) * wes[u + 1];
        }
        p0 += __shfl_xor_sync(0xffffffffu, p0, 1);
        p0 += __shfl_xor_sync(0xffffffffu, p0, 2);
        p1 += __shfl_xor_sync(0xffffffffu, p1, 1);
        p1 += __shfl_xor_sync(0xffffffffu, p1, 2);
        if (tig == 0) {
            red[r0][wid & 1] = p0;
            red[r1][wid & 1] = p1;
        }
    }
    __syncthreads();
    {
        g_E[sb * NT + t0 + tid] = 10.0f * (red[tid][0] + red[tid][1]);
    }
}

// ============================================================================
// K3: softmax over T per (s,b) (unstabilized, matches reference)
// ============================================================================
__global__ void __launch_bounds__(256) k3_softmax() {
    const int sb = blockIdx.x, tid = threadIdx.x;
    __shared__ float ssum[8];
    float a[4], lsum = 0.f;
#pragma unroll
    for (int i = 0; i < 4; i++) {
        a[i] = expf(g_E[sb * NT + tid + i * 256]);
        lsum += a[i];
    }
#pragma unroll
    for (int o = 16; o; o >>= 1) lsum += __shfl_xor_sync(0xffffffffu, lsum, o);
    if ((tid & 31) == 0) ssum[tid >> 5] = lsum;
    __syncthreads();
    if (tid == 0) {
        float sT = 0.f;
#pragma unroll
        for (int q = 0; q < 8; q++) sT += ssum[q];
        ssum[0] = 1.0f / (sT + 1e-7f);
    }
    __syncthreads();
    float inv = ssum[0];
#pragma unroll
    for (int i = 0; i < 4; i++) g_W[sb * NT + tid + i * 256] = a[i] * inv;
}

// ============================================================================
// K4: out = X * ww  (float4 streaming)
// ============================================================================
__global__ void __launch_bounds__(256) k4_scale(const float* __restrict__ x1,
                                                const float* __restrict__ x2,
                                                float* __restrict__ out) {
    size_t f = (size_t)blockIdx.x * 256 + threadIdx.x;
    int d4 = (int)(f & 127);
    int t = (int)((f >> 7) & 1023);
    int sb = (int)(f >> 17);
    const float* __restrict__ X = (sb >= NB) ? x2 : x1;
    int b = sb & 31;
    float w = g_W[sb * NT + t];
    float4 v = *(const float4*)(X + ((size_t)b * NT + t) * ND + (d4 << 2));
    v.x *= w; v.y *= w; v.z *= w; v.w *= w;
    ((float4*)out)[f] = v;
}

extern "C" void kernel_launch(void* const* d_in, const int* in_sizes, int n_in,
                              void* d_out, int out_size) {
    const float* x1 = (const float*)d_in[0];
    const float* x2 = (const float*)d_in[1];
    const float* w1 = (const float*)d_in[2];
    const float* w2 = (const float*)d_in[3];
    const float* w3 = (const float*)d_in[4];
    const float* we = (const float*)d_in[5];
    float* out = (float*)d_out;

    k0_wsplit<<<(512 * 128) / 256, 256>>>(w2, w3);

    dim3 g1(ND / 128, NB, 2);
    k1_xtw<<<g1, 256>>>(x1, x2);

    k_prep<<<(64 * 256 * 64) / 256, 256>>>(w1);

    dim3 g2(NT / 256, NB, 2);
    k2_he<<<g2, 256>>>(x1, x2, we);

    k3_softmax<<<2 * NB, 256>>>();

    k4_scale<<<(2u * NB * NT * (ND / 4)) / 256, 256>>>(x1, x2, out);
}

// round 17
// speedup vs baseline: 1.0472x; 1.0472x over previous
#include <cuda_runtime.h>
#include <cstdint>

#define NB 32
#define NT 1024
#define ND 512
#define NU 64

// -------- scratch (device globals) --------
__device__ float g_C[2ull * NB * ND * 128];   // X^T@[w2|w3] fp32  (16.8MB)
__device__ uint32_t g_WH[512 * 128];          // [t-pair][u] packed f16x2 hi of [w2|w3]
__device__ uint32_t g_WL[512 * 128];          //                  residual lo
__device__ uint32_t g_MH[64ull * 256 * 64];   // [sb][d-pair][u] packed f16x2 hi of M
__device__ uint32_t g_ML[64ull * 256 * 64];
__device__ float g_E[2 * NB * NT];
__device__ float g_W[2 * NB * NT];

// -------- helpers --------
__device__ __forceinline__ uint32_t smem_u32(const void* p) {
    uint32_t a;
    asm("{ .reg .u64 t; cvta.to.shared.u64 t, %1; cvt.u32.u64 %0, t; }" : "=r"(a) : "l"(p));
    return a;
}
// split (x0,x1) -> packed f16x2 hi (lo half = x0) + packed residual lo
__device__ __forceinline__ void split_pair(float x0, float x1, uint32_t& hi, uint32_t& lo) {
    asm("cvt.rn.f16x2.f32 %0, %1, %2;" : "=r"(hi) : "f"(x1), "f"(x0));
    float h0, h1;
    asm("{ .reg .b16 a, b; mov.b32 {a, b}, %2; cvt.f32.f16 %0, a; cvt.f32.f16 %1, b; }"
        : "=f"(h0), "=f"(h1) : "r"(hi));
    float l0 = x0 - h0, l1 = x1 - h1;
    asm("cvt.rn.f16x2.f32 %0, %1, %2;" : "=r"(lo) : "f"(l1), "f"(l0));
}
__device__ __forceinline__ void mma_f16(float* c, const uint32_t* a, const uint32_t* b) {
    asm volatile(
        "mma.sync.aligned.m16n8k16.row.col.f32.f16.f16.f32 "
        "{%0,%1,%2,%3}, {%4,%5,%6,%7}, {%8,%9}, {%0,%1,%2,%3};"
        : "+f"(c[0]), "+f"(c[1]), "+f"(c[2]), "+f"(c[3])
        : "r"(a[0]), "r"(a[1]), "r"(a[2]), "r"(a[3]), "r"(b[0]), "r"(b[1]));
}
__device__ __forceinline__ void cp16(uint32_t dst, const void* src) {
    asm volatile("cp.async.cg.shared.global [%0], [%1], 16;" :: "r"(dst), "l"(src));
}
#define CP_COMMIT() asm volatile("cp.async.commit_group;" ::: "memory")
#define CP_WAIT1() asm volatile("cp.async.wait_group 1;" ::: "memory")
#define CP_WAIT0() asm volatile("cp.async.wait_group 0;" ::: "memory")

// ============================================================================
// K0: pre-split [w2|w3] into packed f16x2 t-pair words.
// ============================================================================
__global__ void __launch_bounds__(256) k0_wsplit(const float* __restrict__ w2,
                                                 const float* __restrict__ w3) {
    int i = blockIdx.x * 256 + threadIdx.x;  // 512*128
    int u = i & 127, tp = i >> 7;
    const float* W = (u < 64) ? (w2 + u) : (w3 + (u - 64));
    float v0 = W[(size_t)(2 * tp) * NU];
    float v1 = W[(size_t)(2 * tp + 1) * NU];
    uint32_t hi, lo;
    split_pair(v0, v1, hi, lo);
    g_WH[i] = hi;
    g_WL[i] = lo;
}

// ============================================================================
// K1: C[s][b] = X_s[b]^T @ [w2|w3]   M=128(d) N=128(u) K=1024(t)
// 8 warps (2M x 4N), warp tile 64x32, Kc=16.
// 3-stage circular buffer, ONE barrier per chunk, 2-deep cp.async prefetch.
// Mainloop identical to R13 (split at fragment load, pass-major mma).
// ============================================================================
#define K1S 132
#define K1BS 136
__global__ void __launch_bounds__(256, 2) k1_xtw(const float* __restrict__ x1,
                                                 const float* __restrict__ x2) {
    __shared__ __align__(16) float sA[3][16][K1S];        // [t][d] fp32
    __shared__ __align__(16) uint32_t sB[3][2][8][K1BS];  // [buf][hi/lo][t-pair][u]
    const int tid = threadIdx.x, wid = tid >> 5, lane = tid & 31;
    const int gid = lane >> 2, tig = lane & 3;
    const int dt = blockIdx.x, b = blockIdx.y, s = blockIdx.z;
    const float* __restrict__ X = s ? x2 : x1;
    const int d0 = dt * 128;
    const int wm = (wid >> 2) * 64, wn = (wid & 3) * 32;

    float acc[4][4][4];
#pragma unroll
    for (int i = 0; i < 4; i++)
#pragma unroll
        for (int j = 0; j < 4; j++)
#pragma unroll
            for (int q = 0; q < 4; q++) acc[i][j][q] = 0.f;

    const uint32_t aB = smem_u32(&sA[0][0][0]);
    const uint32_t bB = smem_u32(&sB[0][0][0][0]);
    const uint32_t aBuf = 16 * K1S * 4;
    const uint32_t bBuf = 2 * 8 * K1BS * 4;

    auto issue = [&](int ch, int bi) {
        const int k0 = ch * 16;
#pragma unroll
        for (int it = 0; it < 2; it++) {
            int ff = tid + it * 256;
            int r = ff >> 5, c = (ff & 31) * 4;
            cp16(aB + bi * aBuf + (uint32_t)(r * K1S + c) * 4,
                 X + ((size_t)b * NT + k0 + r) * ND + d0 + c);
        }
#pragma unroll
        for (int it = 0; it < 2; it++) {
            int ff = tid + it * 256;
            int sp = ff >> 8, r = (ff >> 5) & 7, c = (ff & 31) * 4;
            const uint32_t* src = (sp ? g_WL : g_WH) + (size_t)(ch * 8 + r) * 128 + c;
            cp16(bB + bi * bBuf + (uint32_t)((sp * 8 + r) * K1BS + c) * 4, src);
        }
        CP_COMMIT();
    };

    issue(0, 0);
    issue(1, 1);
    for (int ch = 0; ch < 64; ch++) {
        const int bi = ch % 3;
        if (ch + 1 < 64) {
            CP_WAIT1();  // group for buf bi complete; next group stays in flight
        } else {
            CP_WAIT0();
        }
        __syncthreads();  // arrivals visible; iter ch-1 readers of buf[(ch+2)%3] done
        if (ch + 2 < 64) issue(ch + 2, (ch + 2) % 3);
        const float(*A)[K1S] = sA[bi];
        uint32_t bh[4][2], bl[4][2];
#pragma unroll
        for (int ni = 0; ni < 4; ni++) {
            const int un = wn + ni * 8 + gid;
            bh[ni][0] = sB[bi][0][tig][un];
            bh[ni][1] = sB[bi][0][tig + 4][un];
            bl[ni][0] = sB[bi][1][tig][un];
            bl[ni][1] = sB[bi][1][tig + 4][un];
        }
#pragma unroll
        for (int mi = 0; mi < 4; mi++) {
            const int dm = wm + mi * 16 + gid;
            uint32_t ah[4], al[4];
            split_pair(A[2 * tig][dm], A[2 * tig + 1][dm], ah[0], al[0]);
            split_pair(A[2 * tig][dm + 8], A[2 * tig + 1][dm + 8], ah[1], al[1]);
            split_pair(A[2 * tig + 8][dm], A[2 * tig + 9][dm], ah[2], al[2]);
            split_pair(A[2 * tig + 8][dm + 8], A[2 * tig + 9][dm + 8], ah[3], al[3]);
#pragma unroll
            for (int ni = 0; ni < 4; ni++) mma_f16(acc[mi][ni], ah, bh[ni]);
#pragma unroll
            for (int ni = 0; ni < 4; ni++) mma_f16(acc[mi][ni], al, bh[ni]);
#pragma unroll
            for (int ni = 0; ni < 4; ni++) mma_f16(acc[mi][ni], ah, bl[ni]);
        }
        __syncthreads();  // readers of buf bi done before it is overwritten at ch+3
    }
    float* dst = g_C + (size_t)(s * NB + b) * ND * 128 + (size_t)d0 * 128;
#pragma unroll
    for (int mi = 0; mi < 4; mi++) {
        int r0 = wm + mi * 16 + gid, r1 = r0 + 8;
#pragma unroll
        for (int ni = 0; ni < 4; ni++) {
            int col = wn + ni * 8 + 2 * tig;
            *(float2*)(dst + (size_t)r0 * 128 + col) =
                make_float2(acc[mi][ni][0], acc[mi][ni][1]);
            *(float2*)(dst + (size_t)r1 * 128 + col) =
                make_float2(acc[mi][ni][2], acc[mi][ni][3]);
        }
    }
}

// ============================================================================
// K_prep: M[sb][d][u] = C[1-s][b][d][u] + C[s][b][d][64+u] + w1[d][u]
// -> packed f16x2 d-pair words g_MH/g_ML [sb][dp][u]
// ============================================================================
__global__ void __launch_bounds__(256) k_prep(const float* __restrict__ w1) {
    int i = blockIdx.x * 256 + threadIdx.x;  // 64*256*64 = 1,048,576
    int u = i & 63;
    int dp = (i >> 6) & 255;
    int sb = i >> 14;
    int s = sb >> 5, b = sb & 31;
    const float* C0 = g_C + ((size_t)((1 - s) * NB + b) * ND << 7);
    const float* C1 = g_C + ((size_t)sb * ND << 7);
    int d0 = 2 * dp, d1 = 2 * dp + 1;
    float m0 = C0[((size_t)d0 << 7) + u] + C1[((size_t)d0 << 7) + 64 + u] + w1[d0 * NU + u];
    float m1 = C0[((size_t)d1 << 7) + u] + C1[((size_t)d1 << 7) + 64 + u] + w1[d1 * NU + u];
    uint32_t hi, lo;
    split_pair(m0, m1, hi, lo);
    g_MH[i] = hi;
    g_ML[i] = lo;
}

// ============================================================================
// K2: e = 10*sum_u tanh(X@M)*we    M=256(t) N=64(u) K=512(d)
// grid 256 (single wave). 8 warps (4M x 2N), warp tile 64t x 32u, Kc=16.
// 3-stage circular buffer, ONE barrier per chunk. Mainloop = R13.
// ============================================================================
#define K2AS 20
#define K2BS 72
__global__ void __launch_bounds__(256, 2) k2_he(const float* __restrict__ x1,
                                                const float* __restrict__ x2,
                                                const float* __restrict__ we) {
    __shared__ __align__(16) float sA[3][256][K2AS];      // [t][d] fp32
    __shared__ __align__(16) uint32_t sB[3][2][8][K2BS];  // [buf][hi/lo][d-pair][u]
    __shared__ float wes[64];
    __shared__ float red[256][2];
    const int tid = threadIdx.x, wid = tid >> 5, lane = tid & 31;
    const int gid = lane >> 2, tig = lane & 3;
    const int tt = blockIdx.x, b = blockIdx.y, s = blockIdx.z;
    const float* __restrict__ X = s ? x2 : x1;
    const int t0 = tt * 256, sb = s * NB + b;
    const int wm = (wid >> 1) * 64, wn = (wid & 1) * 32;

    if (tid < 64) wes[tid] = we[tid];

    float acc[4][4][4];
#pragma unroll
    for (int i = 0; i < 4; i++)
#pragma unroll
        for (int j = 0; j < 4; j++)
#pragma unroll
            for (int q = 0; q < 4; q++) acc[i][j][q] = 0.f;

    const uint32_t aB = smem_u32(&sA[0][0][0]);
    const uint32_t bB = smem_u32(&sB[0][0][0][0]);
    const uint32_t aBuf = 256 * K2AS * 4;
    const uint32_t bBuf = 2 * 8 * K2BS * 4;
    const size_t mBase = (size_t)sb * 256 * 64;

    auto issue = [&](int ch, int bi) {
        const int k0 = ch * 16;
#pragma unroll
        for (int it = 0; it < 4; it++) {
            int ff = tid + it * 256;
            int r = ff >> 2, c = (ff & 3) * 4;
            cp16(aB + bi * aBuf + (uint32_t)(r * K2AS + c) * 4,
                 X + ((size_t)b * NT + t0 + r) * ND + k0 + c);
        }
        {
            int sp = tid >> 7, r = (tid >> 4) & 7, c = (tid & 15) * 4;
            const uint32_t* src = (sp ? g_ML : g_MH) + mBase + (size_t)(ch * 8 + r) * 64 + c;
            cp16(bB + bi * bBuf + (uint32_t)((sp * 8 + r) * K2BS + c) * 4, src);
        }
        CP_COMMIT();
    };

    issue(0, 0);
    issue(1, 1);
    for (int ch = 0; ch < 32; ch++) {
        const int bi = ch % 3;
        if (ch + 1 < 32) {
            CP_WAIT1();
        } else {
            CP_WAIT0();
        }
        __syncthreads();
        if (ch + 2 < 32) issue(ch + 2, (ch + 2) % 3);
        const float(*A)[K2AS] = sA[bi];
        uint32_t bh[4][2], bl[4][2];
#pragma unroll
        for (int ni = 0; ni < 4; ni++) {
            const int un = wn + ni * 8 + gid;
            bh[ni][0] = sB[bi][0][tig][un];
            bh[ni][1] = sB[bi][0][tig + 4][un];
            bl[ni][0] = sB[bi][1][tig][un];
            bl[ni][1] = sB[bi][1][tig + 4][un];
        }
#pragma unroll
        for (int mi = 0; mi < 4; mi++) {
            const int tr = wm + mi * 16 + gid;
            uint32_t ah[4], al[4];
            {
                float2 v = *(const float2*)&A[tr][2 * tig];
                split_pair(v.x, v.y, ah[0], al[0]);
            }
            {
                float2 v = *(const float2*)&A[tr + 8][2 * tig];
                split_pair(v.x, v.y, ah[1], al[1]);
            }
            {
                float2 v = *(const float2*)&A[tr][2 * tig + 8];
                split_pair(v.x, v.y, ah[2], al[2]);
            }
            {
                float2 v = *(const float2*)&A[tr + 8][2 * tig + 8];
                split_pair(v.x, v.y, ah[3], al[3]);
            }
#pragma unroll
            for (int ni = 0; ni < 4; ni++) mma_f16(acc[mi][ni], ah, bh[ni]);
#pragma unroll
            for (int ni = 0; ni < 4; ni++) mma_f16(acc[mi][ni], al, bh[ni]);
#pragma unroll
            for (int ni = 0; ni < 4; ni++) mma_f16(acc[mi][ni], ah, bl[ni]);
        }
        __syncthreads();
    }
    // epilogue: e(t) = 10 * sum_u tanh(h[t,u]) * we[u]
#pragma unroll
    for (int mi = 0; mi < 4; mi++) {
        int r0 = wm + mi * 16 + gid, r1 = r0 + 8;
        float p0 = 0.f, p1 = 0.f;
#pragma unroll
        for (int ni = 0; ni < 4; ni++) {
            int u = wn + ni * 8 + 2 * tig;
            p0 += tanhf(acc[mi][ni][0]) * wes[u] + tanhf(acc[mi][ni][1]) * wes[u + 1];
            p1 += tanhf(acc[mi][ni][2]) * wes[u] + tanhf(acc[mi][ni][3]) * wes[u + 1];
        }
        p0 += __shfl_xor_sync(0xffffffffu, p0, 1);
        p0 += __shfl_xor_sync(0xffffffffu, p0, 2);
        p1 += __shfl_xor_sync(0xffffffffu, p1, 1);
        p1 += __shfl_xor_sync(0xffffffffu, p1, 2);
        if (tig == 0) {
            red[r0][wid & 1] = p0;
            red[r1][wid & 1] = p1;
        }
    }
    __syncthreads();
    {
        g_E[sb * NT + t0 + tid] = 10.0f * (red[tid][0] + red[tid][1]);
    }
}

// ============================================================================
// K3: softmax over T per (s,b) (unstabilized, matches reference)
// ============================================================================
__global__ void __launch_bounds__(256) k3_softmax() {
    const int sb = blockIdx.x, tid = threadIdx.x;
    __shared__ float ssum[8];
    float a[4], lsum = 0.f;
#pragma unroll
    for (int i = 0; i < 4; i++) {
        a[i] = expf(g_E[sb * NT + tid + i * 256]);
        lsum += a[i];
    }
#pragma unroll
    for (int o = 16; o; o >>= 1) lsum += __shfl_xor_sync(0xffffffffu, lsum, o);
    if ((tid & 31) == 0) ssum[tid >> 5] = lsum;
    __syncthreads();
    if (tid == 0) {
        float sT = 0.f;
#pragma unroll
        for (int q = 0; q < 8; q++) sT += ssum[q];
        ssum[0] = 1.0f / (sT + 1e-7f);
    }
    __syncthreads();
    float inv = ssum[0];
#pragma unroll
    for (int i = 0; i < 4; i++) g_W[sb * NT + tid + i * 256] = a[i] * inv;
}

// ============================================================================
// K4: out = X * ww  (float4 streaming)
// ============================================================================
__global__ void __launch_bounds__(256) k4_scale(const float* __restrict__ x1,
                                                const float* __restrict__ x2,
                                                float* __restrict__ out) {
    size_t f = (size_t)blockIdx.x * 256 + threadIdx.x;
    int d4 = (int)(f & 127);
    int t = (int)((f >> 7) & 1023);
    int sb = (int)(f >> 17);
    const float* __restrict__ X = (sb >= NB) ? x2 : x1;
    int b = sb & 31;
    float w = g_W[sb * NT + t];
    float4 v = *(const float4*)(X + ((size_t)b * NT + t) * ND + (d4 << 2));
    v.x *= w; v.y *= w; v.z *= w; v.w *= w;
    ((float4*)out)[f] = v;
}

extern "C" void kernel_launch(void* const* d_in, const int* in_sizes, int n_in,
                              void* d_out, int out_size) {
    const float* x1 = (const float*)d_in[0];
    const float* x2 = (const float*)d_in[1];
    const float* w1 = (const float*)d_in[2];
    const float* w2 = (const float*)d_in[3];
    const float* w3 = (const float*)d_in[4];
    const float* we = (const float*)d_in[5];
    float* out = (float*)d_out;

    k0_wsplit<<<(512 * 128) / 256, 256>>>(w2, w3);

    dim3 g1(ND / 128, NB, 2);
    k1_xtw<<<g1, 256>>>(x1, x2);

    k_prep<<<(64 * 256 * 64) / 256, 256>>>(w1);

    dim3 g2(NT / 256, NB, 2);
    k2_he<<<g2, 256>>>(x1, x2, we);

    k3_softmax<<<2 * NB, 256>>>();

    k4_scale<<<(2u * NB * NT * (ND / 4)) / 256, 256>>>(x1, x2, out);
}